// round 6
// baseline (speedup 1.0000x reference)
#include <cuda_runtime.h>
#include <math.h>

constexpr int Bn = 2, Nn = 1024, Cc = 512, Hc = 8, Dc = 64, Mc = 128, BHc = 16;

// ---------------- scratch ----------------------------------------------------
__device__ float g_qkv [Bn*Nn*3*Cc];
__device__ float g_pms [Bn*Mc];
__device__ float g_lmask[Bn*Mc];
__device__ float g_valid[1];
__device__ float g_fro [BHc];
__device__ float g_ql  [BHc*Mc*Dc];
__device__ float g_kl  [BHc*Mc*Dc];
__device__ float g_Weps[BHc*Mc*Mc];
__device__ float g_Xa  [BHc*Mc*Mc];
__device__ float g_Xb  [BHc*Mc*Mc];
__device__ float g_T   [BHc*Mc*Mc];
__device__ float g_Cq  [BHc*Nn*Mc];
__device__ float g_Ck  [BHc*Nn*Mc];
__device__ float g_stats[4*Hc*Mc];
__device__ float g_mu  [Hc*Mc];
__device__ float g_rstd[Hc*Mc];
__device__ float g_ckvp[BHc*8*Mc*Dc];
__device__ float g_ctx [BHc*Mc*Dc];
__device__ float g_gab [Bn*Nn*Cc];

// ---------------- f32x2 helpers ---------------------------------------------
typedef unsigned long long ull;
__device__ __forceinline__ void ffma2(ull& d, ull a, ull b) {
    asm("fma.rn.f32x2 %0, %1, %2, %0;" : "+l"(d) : "l"(a), "l"(b));
}
__device__ __forceinline__ ull add2(ull a, ull b) {
    ull d; asm("add.rn.f32x2 %0, %1, %2;" : "=l"(d) : "l"(a), "l"(b)); return d;
}
__device__ __forceinline__ ull dup2(float x) {
    ull u; asm("mov.b64 %0,{%1,%2};" : "=l"(u) : "f"(x), "f"(x)); return u;
}
__device__ __forceinline__ float2 unpack2(ull u) {
    float2 v; asm("mov.b64 {%0,%1},%2;" : "=f"(v.x), "=f"(v.y) : "l"(u)); return v;
}
constexpr ull ABS2 = 0x7fffffff7fffffffULL;

// ---------------- GEMM: out = (A @ W^T + bias) * tm[row] ---------------------
// 128x64 tile, 16x16 threads. A stored DUPLICATED in smem so LDS.64 yields
// {a,a} directly (no MOV dup). Inner loop: 8 LDS.64 A + 2 LDS.64 B + 16 FFMA2.
__global__ __launch_bounds__(256) void gemm_bias_mask(
        const float* __restrict__ A, const float* __restrict__ W,
        const float* __restrict__ bias, const float* __restrict__ tm,
        float* __restrict__ out, int M, int Nout, int K)
{
    __shared__ float Ad[16 * 258];   // [kk][2*r .. 2*r+1] duplicated
    __shared__ float Bs[16 * 66];
    int tx = threadIdx.x, ty = threadIdx.y;
    int tid = ty * 16 + tx;
    int rb = blockIdx.y * 128, cb = blockIdx.x * 64;
    ull acc[8][2] = {};
    for (int k0 = 0; k0 < K; k0 += 16) {
#pragma unroll
        for (int l = 0; l < 8; l++) {
            int e = tid + l * 256;
            int r = e >> 4, kk = e & 15;
            float a = A[(rb + r) * K + k0 + kk];
            *(float2*)&Ad[kk * 258 + 2 * r] = make_float2(a, a);
        }
#pragma unroll
        for (int l = 0; l < 4; l++) {
            int e = tid + l * 256;
            int r = e >> 4, kk = e & 15;
            Bs[kk * 66 + r] = W[(cb + r) * K + k0 + kk];
        }
        __syncthreads();
#pragma unroll
        for (int kk = 0; kk < 16; kk++) {
            ull ad[8];
#pragma unroll
            for (int a = 0; a < 8; a++) ad[a] = *(const ull*)&Ad[kk * 258 + 2 * (ty + 16 * a)];
            ull b0 = *(const ull*)&Bs[kk * 66 + 2 * tx];
            ull b1 = *(const ull*)&Bs[kk * 66 + 2 * tx + 32];
#pragma unroll
            for (int a = 0; a < 8; a++) {
                ffma2(acc[a][0], ad[a], b0);
                ffma2(acc[a][1], ad[a], b1);
            }
        }
        __syncthreads();
    }
    float2 bia0 = *(const float2*)&bias[cb + 2 * tx];
    float2 bia1 = *(const float2*)&bias[cb + 2 * tx + 32];
#pragma unroll
    for (int a = 0; a < 8; a++) {
        int row = rb + ty + 16 * a;
        float t = tm[row];
        float2 v0 = unpack2(acc[a][0]);
        float2 v1 = unpack2(acc[a][1]);
        v0.x = (v0.x + bia0.x) * t; v0.y = (v0.y + bia0.y) * t;
        v1.x = (v1.x + bia1.x) * t; v1.y = (v1.y + bia1.y) * t;
        *(float2*)&out[row * Nout + cb + 2 * tx] = v0;
        *(float2*)&out[row * Nout + cb + 2 * tx + 32] = v1;
    }
}

// ---------------- batched NS matmul: 32x64 tiles, dup'd A --------------------
__global__ __launch_bounds__(256) void ns_mm(
        const float* __restrict__ A, const float* __restrict__ Bm,
        float* __restrict__ Out, int mode)
{
    __shared__ float Ad[16 * 66];    // 32 rows duplicated
    __shared__ float Bs[16 * 66];
    int tx = threadIdx.x, ty = threadIdx.y;
    int tid = ty * 16 + tx;
    int batch = blockIdx.z;
    const float* Ab = A + batch * Mc * Mc;
    const float* Bb = Bm + batch * Mc * Mc;
    float* Ob = Out + batch * Mc * Mc;
    int rb = blockIdx.y * 32, cb = blockIdx.x * 64;
    ull acc[2][2] = {};
    for (int k0 = 0; k0 < 128; k0 += 16) {
#pragma unroll
        for (int l = 0; l < 2; l++) {
            int e = tid + l * 256;
            int r = e >> 4, kk = e & 15;
            float a = Ab[(rb + r) * 128 + k0 + kk];
            *(float2*)&Ad[kk * 66 + 2 * r] = make_float2(a, a);
        }
#pragma unroll
        for (int l = 0; l < 4; l++) {
            int e = tid + l * 256;
            int kb = e >> 6, j = e & 63;
            Bs[kb * 66 + j] = Bb[(k0 + kb) * 128 + cb + j];
        }
        __syncthreads();
#pragma unroll
        for (int kk = 0; kk < 16; kk++) {
            ull a0 = *(const ull*)&Ad[kk * 66 + 2 * ty];
            ull a1 = *(const ull*)&Ad[kk * 66 + 2 * (ty + 16)];
            ull b0 = *(const ull*)&Bs[kk * 66 + 2 * tx];
            ull b1 = *(const ull*)&Bs[kk * 66 + 2 * tx + 32];
            ffma2(acc[0][0], a0, b0);
            ffma2(acc[0][1], a0, b1);
            ffma2(acc[1][0], a1, b0);
            ffma2(acc[1][1], a1, b1);
        }
        __syncthreads();
    }
#pragma unroll
    for (int a = 0; a < 2; a++) {
        int i = rb + ty + 16 * a;
#pragma unroll
        for (int c = 0; c < 2; c++) {
            int j0 = cb + 2 * tx + 32 * c;
            float2 v = unpack2(acc[a][c]);
            if (mode) {
                v.x = ((i == j0)     ? 2.f : 0.f) - v.x;
                v.y = ((i == j0 + 1) ? 2.f : 0.f) - v.y;
            }
            *(float2*)&Ob[i * 128 + j0] = v;
        }
    }
}

// ---------------- pooled-mask stats (+ zero g_stats, g_fro) ------------------
__global__ void pm_kernel(const float* __restrict__ tm)
{
    __shared__ float red[256];
    int t = threadIdx.x;
    int b = t >> 7, mm = t & 127;
    if (t < BHc) g_fro[t] = 0.f;
    for (int e = t; e < 4 * Hc * Mc; e += 256) g_stats[e] = 0.f;
    float s = 0.f;
#pragma unroll
    for (int j = 0; j < 8; j++) s += tm[b * Nn + mm * 8 + j];
    float pm = s * 0.125f;
    g_pms[t] = fmaxf(pm, 1e-6f);
    g_lmask[t] = pm > 0.f ? 1.f : 0.f;
    red[t] = s;
    __syncthreads();
    for (int o = 128; o > 0; o >>= 1) {
        if (t < o) red[t] += red[t + o];
        __syncthreads();
    }
    if (t == 0) g_valid[0] = fmaxf(red[0], 1.f);
}

// ---------------- pooled q_l / k_l: coalesced float4 loads -------------------
__global__ void pool_kernel(const float* __restrict__ tm)
{
    int i = blockIdx.x * 256 + threadIdx.x;
    int mm = i & 127;
    int d  = (i >> 7) & 63;
    int h  = (i >> 13) & 7;
    int b  = (i >> 16) & 1;
    int s  = i >> 17;
    int c = h * 64 + d;
    int f0 = c * 1024 + mm * 8;
    int n = f0 >> 9, hd = f0 & 511;
    const float4* p = (const float4*)&g_qkv[(b * Nn + n) * 1536 + s * 512 + hd];
    float4 v0 = p[0], v1 = p[1];
    const float4* tp = (const float4*)&tm[b * Nn + mm * 8];
    float4 t0 = tp[0], t1 = tp[1];
    float acc = v0.x * t0.x + v0.y * t0.y + v0.z * t0.z + v0.w * t0.w
              + v1.x * t1.x + v1.y * t1.y + v1.z * t1.z + v1.w * t1.w;
    acc = acc * 0.125f / g_pms[b * 128 + mm];
    float* dst = (s == 0) ? g_ql : g_kl;
    dst[((b * 8 + h) * 128 + mm) * 64 + d] = acc;
}

// ---------------- W_eps: 32x32 tiles, f32x2 abs-sum --------------------------
__global__ __launch_bounds__(256) void buildW_A()
{
    __shared__ float sql[32 * 66];
    __shared__ float skn[32 * 66];   // negated kl
    int tx = threadIdx.x, ty = threadIdx.y;
    int tid = ty * 16 + tx;
    int batch = blockIdx.z;
    int b = batch >> 3;
    int rb = blockIdx.y * 32, cb = blockIdx.x * 32;
    for (int e = tid; e < 2048; e += 256) {
        int r = e >> 6, d = e & 63;
        sql[r * 66 + d] = g_ql[batch * 8192 + (rb + r) * 64 + d];
        skn[r * 66 + d] = -g_kl[batch * 8192 + (cb + r) * 64 + d];
    }
    __syncthreads();
    ull acc[2][2] = {};
    for (int dp = 0; dp < 32; dp++) {
        ull q0 = *(const ull*)&sql[ty * 66 + 2 * dp];
        ull q1 = *(const ull*)&sql[(ty + 16) * 66 + 2 * dp];
        ull k0 = *(const ull*)&skn[tx * 66 + 2 * dp];
        ull k1 = *(const ull*)&skn[(tx + 16) * 66 + 2 * dp];
        ull t;
        t = add2(q0, k0) & ABS2; acc[0][0] = add2(acc[0][0], t);
        t = add2(q0, k1) & ABS2; acc[0][1] = add2(acc[0][1], t);
        t = add2(q1, k0) & ABS2; acc[1][0] = add2(acc[1][0], t);
        t = add2(q1, k1) & ABS2; acc[1][1] = add2(acc[1][1], t);
    }
    float fro = 0.f;
#pragma unroll
    for (int a = 0; a < 2; a++)
#pragma unroll
        for (int bb = 0; bb < 2; bb++) {
            int i = rb + ty + 16 * a;
            int j = cb + tx + 16 * bb;
            float2 v = unpack2(acc[a][bb]);
            float l1 = v.x + v.y;
            float w = __expf(-l1 * 0.25f);
            float pair = g_lmask[b * 128 + i] * g_lmask[b * 128 + j];
            float diag = (i == j) ? 1.f : 0.f;
            w = w * pair + diag * (1.f - pair) + diag * 1e-4f;
            g_Weps[batch * 16384 + i * 128 + j] = w;
            fro += w * w;
        }
#pragma unroll
    for (int o = 16; o > 0; o >>= 1)
        fro += __shfl_xor_sync(0xffffffffu, fro, o);
    if ((tid & 31) == 0) atomicAdd(&g_fro[batch], fro);
}

// X0 = (2/(||Weps||_F + 1e-8)) * Weps^T
__global__ void buildW_B()
{
    int batch = blockIdx.x;
    int tid = threadIdx.x;
    float s = 2.f / (sqrtf(g_fro[batch]) + 1e-8f);
    for (int e = tid; e < 16384; e += 256) {
        int i = e >> 7, j = e & 127;
        g_Xa[batch * 16384 + j * 128 + i] = s * g_Weps[batch * 16384 + e];
    }
}

// ---------------- C_q / C_k laplacian: f32x2 abs-sum -------------------------
// grid (16 n-tiles of 64, 2 j-tiles of 64, 16 batch). block 16x16.
__global__ __launch_bounds__(256) void lap_kernel(const float* __restrict__ tm)
{
    extern __shared__ float sh[];
    float* sqn_ = sh;                 // -ql tile   64*66
    float* skn_ = sqn_ + 64 * 66;     // -kl tile   64*66
    float* sq   = skn_ + 64 * 66;     // q rows     64*66
    float* sk   = sq   + 64 * 66;     // k rows     64*66
    int tx = threadIdx.x, ty = threadIdx.y;
    int tid = ty * 16 + tx;
    int batch = blockIdx.z;
    int b = batch >> 3, h = batch & 7;
    int n0 = blockIdx.x * 64;
    int jb = blockIdx.y * 64;
    for (int e = tid; e < 4096; e += 256) {
        int r = e >> 6, d = e & 63;
        sqn_[r * 66 + d] = -g_ql[batch * 8192 + (jb + r) * 64 + d];
        skn_[r * 66 + d] = -g_kl[batch * 8192 + (jb + r) * 64 + d];
        const float* row = &g_qkv[(b * Nn + n0 + r) * 1536 + h * 64];
        sq[r * 66 + d] = row[d];
        sk[r * 66 + d] = row[512 + d];
    }
    __syncthreads();
    ull accq[4][4] = {}, acck[4][4] = {};
    for (int dp = 0; dp < 32; dp++) {
        ull qf[4], kf[4], qn[4], kn[4];
#pragma unroll
        for (int a = 0; a < 4; a++) {
            qf[a] = *(const ull*)&sq[(ty + 16 * a) * 66 + 2 * dp];
            kf[a] = *(const ull*)&sk[(ty + 16 * a) * 66 + 2 * dp];
        }
#pragma unroll
        for (int bb = 0; bb < 4; bb++) {
            qn[bb] = *(const ull*)&sqn_[(tx + 16 * bb) * 66 + 2 * dp];
            kn[bb] = *(const ull*)&skn_[(tx + 16 * bb) * 66 + 2 * dp];
        }
#pragma unroll
        for (int a = 0; a < 4; a++)
#pragma unroll
            for (int bb = 0; bb < 4; bb++) {
                ull t1 = add2(qf[a], kn[bb]) & ABS2;
                accq[a][bb] = add2(accq[a][bb], t1);
                ull t2 = add2(kf[a], qn[bb]) & ABS2;
                acck[a][bb] = add2(acck[a][bb], t2);
            }
    }
#pragma unroll
    for (int a = 0; a < 4; a++)
#pragma unroll
        for (int bb = 0; bb < 4; bb++) {
            int n = n0 + ty + 16 * a;
            int j = jb + tx + 16 * bb;
            float lm = g_lmask[b * 128 + j];
            float2 vq = unpack2(accq[a][bb]);
            float2 vk = unpack2(acck[a][bb]);
            g_Cq[(batch * Nn + n) * 128 + j] = __expf(-(vq.x + vq.y) * 0.25f) * lm;
            g_Ck[(batch * Nn + n) * 128 + j] = __expf(-(vk.x + vk.y) * 0.25f) * lm;
        }
}

// ---------------- whitening stats --------------------------------------------
__global__ void stats_part(const float* __restrict__ tm)
{
    int h = blockIdx.y;
    int s = blockIdx.x;
    int j = threadIdx.x;
    float a1 = 0.f, b0 = 0.f, b1 = 0.f, b2 = 0.f;
    for (int r = 0; r < 128; r++) {
        int row = s * 128 + r;
        int b = row >> 10, n = row & 1023;
        float t = tm[row];
        float c = g_Cq[((b * 8 + h) * Nn + n) * 128 + j];
        float tc = t * c;
        a1 += tc;
        b0 += t * t;
        b1 += t * tc;
        b2 += tc * tc;
    }
    atomicAdd(&g_stats[0 * 1024 + h * 128 + j], a1);
    atomicAdd(&g_stats[1 * 1024 + h * 128 + j], b0);
    atomicAdd(&g_stats[2 * 1024 + h * 128 + j], b1);
    atomicAdd(&g_stats[3 * 1024 + h * 128 + j], b2);
}

__global__ void stats_fin()
{
    int i = blockIdx.x * 256 + threadIdx.x;
    if (i >= Hc * Mc) return;
    float valid = g_valid[0];
    float a1 = g_stats[i], b0 = g_stats[1024 + i], b1 = g_stats[2048 + i], b2 = g_stats[3072 + i];
    float mu = a1 / valid;
    float var = (b2 - 2.f * mu * b1 + mu * mu * b0) / valid;
    g_mu[i] = mu;
    g_rstd[i] = 1.f / sqrtf(var + 1e-5f);
}

// ---------------- ckv partials (f32x2 along d) -------------------------------
__global__ void ckv_part_kernel()
{
    extern __shared__ float sh[];
    float* sCk = sh;
    float* sV  = sh + 16384;
    int tx = threadIdx.x, ty = threadIdx.y;
    int tid = ty * 16 + tx;
    int batch = blockIdx.y, split = blockIdx.x;
    int b = batch >> 3, h = batch & 7;
    int n0 = split * 128;
    for (int e = tid; e < 16384; e += 256)
        sCk[e] = g_Ck[(batch * Nn + n0 + (e >> 7)) * 128 + (e & 127)];
    for (int e = tid; e < 8192; e += 256)
        sV[e] = g_qkv[(b * Nn + n0 + (e >> 6)) * 1536 + 1024 + h * 64 + (e & 63)];
    __syncthreads();
    ull acc[8][2] = {};
    for (int n = 0; n < 128; n++) {
        ull cd[8];
#pragma unroll
        for (int a = 0; a < 8; a++) cd[a] = dup2(sCk[n * 128 + ty + 16 * a]);
        ull v0 = *(const ull*)&sV[n * 64 + 2 * tx];
        ull v1 = *(const ull*)&sV[n * 64 + 2 * tx + 32];
#pragma unroll
        for (int a = 0; a < 8; a++) {
            ffma2(acc[a][0], cd[a], v0);
            ffma2(acc[a][1], cd[a], v1);
        }
    }
#pragma unroll
    for (int a = 0; a < 8; a++) {
        int j = ty + 16 * a;
        float* dst = &g_ckvp[((batch * 8 + split) * 128 + j) * 64];
        *(float2*)&dst[2 * tx]      = unpack2(acc[a][0]);
        *(float2*)&dst[2 * tx + 32] = unpack2(acc[a][1]);
    }
}

// ---------------- context = W_inv @ ckv --------------------------------------
__global__ void ctx_kernel()
{
    extern __shared__ float sh[];
    float* sW = sh;
    float* sC = sh + 16384;
    int tx = threadIdx.x, ty = threadIdx.y;
    int tid = ty * 16 + tx;
    int batch = blockIdx.x;
    for (int e = tid; e < 16384; e += 256)
        sW[e] = g_Xb[batch * 16384 + e];
    for (int e = tid; e < 8192; e += 256) {
        float s = 0.f;
#pragma unroll
        for (int p = 0; p < 8; p++) s += g_ckvp[(batch * 8 + p) * 8192 + e];
        sC[e] = s;
    }
    __syncthreads();
    ull acc[8][2] = {};
    for (int j = 0; j < 128; j++) {
        ull wd[8];
#pragma unroll
        for (int a = 0; a < 8; a++) wd[a] = dup2(sW[(ty + 16 * a) * 128 + j]);
        ull c0 = *(const ull*)&sC[j * 64 + 2 * tx];
        ull c1 = *(const ull*)&sC[j * 64 + 2 * tx + 32];
#pragma unroll
        for (int a = 0; a < 8; a++) {
            ffma2(acc[a][0], wd[a], c0);
            ffma2(acc[a][1], wd[a], c1);
        }
    }
#pragma unroll
    for (int a = 0; a < 8; a++) {
        float* dst = &g_ctx[batch * 8192 + (ty + 16 * a) * 64];
        *(float2*)&dst[2 * tx]      = unpack2(acc[a][0]);
        *(float2*)&dst[2 * tx + 32] = unpack2(acc[a][1]);
    }
}

// ---------------- ga = (C_q_norm @ context) * mh -----------------------------
__global__ void ga_kernel(const float* __restrict__ tm)
{
    extern __shared__ float sh[];
    float* sCq = sh;
    float* sC  = sh + 16384;
    int tx = threadIdx.x, ty = threadIdx.y;
    int tid = ty * 16 + tx;
    int batch = blockIdx.y, nt = blockIdx.x;
    int b = batch >> 3, h = batch & 7;
    int n0 = nt * 128;
    for (int e = tid; e < 16384; e += 256) {
        int nl = e >> 7, j = e & 127;
        float t = tm[b * Nn + n0 + nl];
        sCq[e] = (g_Cq[(batch * Nn + n0 + nl) * 128 + j] - g_mu[h * 128 + j]) * g_rstd[h * 128 + j] * t;
    }
    for (int e = tid; e < 8192; e += 256)
        sC[e] = g_ctx[batch * 8192 + e];
    __syncthreads();
    ull acc[8][2] = {};
    for (int j = 0; j < 128; j++) {
        ull qd[8];
#pragma unroll
        for (int a = 0; a < 8; a++) qd[a] = dup2(sCq[(ty + 16 * a) * 128 + j]);
        ull c0 = *(const ull*)&sC[j * 64 + 2 * tx];
        ull c1 = *(const ull*)&sC[j * 64 + 2 * tx + 32];
#pragma unroll
        for (int a = 0; a < 8; a++) {
            ffma2(acc[a][0], qd[a], c0);
            ffma2(acc[a][1], qd[a], c1);
        }
    }
#pragma unroll
    for (int a = 0; a < 8; a++) {
        int n = n0 + ty + 16 * a;
        float t = tm[b * Nn + n];
        float2 v0 = unpack2(acc[a][0]);
        float2 v1 = unpack2(acc[a][1]);
        v0.x *= t; v0.y *= t; v1.x *= t; v1.y *= t;
        float* dst = &g_gab[(b * Nn + n) * 512 + h * 64];
        *(float2*)&dst[2 * tx]      = v0;
        *(float2*)&dst[2 * tx + 32] = v1;
    }
}

// ---------------- depthwise "conv" on the scrambled flat view ----------------
__global__ void vlocal_kernel(const float* __restrict__ tm, const float* __restrict__ dw,
                              const float* __restrict__ db)
{
    int i = blockIdx.x * 256 + threadIdx.x;
    int n2 = i & 1023;
    int ch = (i >> 10) & 511;
    int b  = i >> 19;
    float w0 = dw[ch * 3 + 0], w1 = dw[ch * 3 + 1], w2 = dw[ch * 3 + 2];
    int f = ch * 1024 + n2;
    float acc = db[ch];
    if (n2 > 0) {
        int ff = f - 1;
        acc += w0 * g_qkv[(b * Nn + (ff >> 9)) * 1536 + 1024 + (ff & 511)];
    }
    acc += w1 * g_qkv[(b * Nn + (f >> 9)) * 1536 + 1024 + (f & 511)];
    if (n2 < 1023) {
        int ff = f + 1;
        acc += w2 * g_qkv[(b * Nn + (ff >> 9)) * 1536 + 1024 + (ff & 511)];
    }
    g_gab[(b * Nn + n2) * 512 + ch] += acc * tm[b * Nn + n2];
}

// ---------------- launch -----------------------------------------------------
extern "C" void kernel_launch(void* const* d_in, const int* in_sizes, int n_in,
                              void* d_out, int out_size)
{
    const float* x      = (const float*)d_in[0];
    const float* tm     = (const float*)d_in[1];
    const float* qkv_w  = (const float*)d_in[2];
    const float* qkv_b  = (const float*)d_in[3];
    const float* proj_w = (const float*)d_in[4];
    const float* proj_b = (const float*)d_in[5];
    const float* dwc_w  = (const float*)d_in[6];
    const float* dwc_b  = (const float*)d_in[7];
    float* out = (float*)d_out;

    float *p_qkv, *p_gab, *p_Weps, *p_Xa, *p_Xb, *p_T;
    cudaGetSymbolAddress((void**)&p_qkv,  g_qkv);
    cudaGetSymbolAddress((void**)&p_gab,  g_gab);
    cudaGetSymbolAddress((void**)&p_Weps, g_Weps);
    cudaGetSymbolAddress((void**)&p_Xa,   g_Xa);
    cudaGetSymbolAddress((void**)&p_Xb,   g_Xb);
    cudaGetSymbolAddress((void**)&p_T,    g_T);

    cudaFuncSetAttribute(lap_kernel,      cudaFuncAttributeMaxDynamicSharedMemorySize, 4 * 64 * 66 * 4);
    cudaFuncSetAttribute(ckv_part_kernel, cudaFuncAttributeMaxDynamicSharedMemorySize, 98304);
    cudaFuncSetAttribute(ctx_kernel,      cudaFuncAttributeMaxDynamicSharedMemorySize, 98304);
    cudaFuncSetAttribute(ga_kernel,       cudaFuncAttributeMaxDynamicSharedMemorySize, 98304);

    dim3 blk(16, 16);

    // 1. masked QKV projection (128x64 tiles)
    gemm_bias_mask<<<dim3(1536 / 64, 2048 / 128), blk>>>(x, qkv_w, qkv_b, tm, p_qkv,
                                                         Bn * Nn, 3 * Cc, Cc);
    // 2. pooled-mask stats + pooled q_l/k_l
    pm_kernel<<<1, 256>>>(tm);
    pool_kernel<<<1024, 256>>>(tm);

    // 3. W_eps + X0, Newton-Schulz (5 iters)
    buildW_A<<<dim3(4, 4, 16), blk>>>();
    buildW_B<<<16, 256>>>();
    float* Xc = p_Xa;
    float* Xn = p_Xb;
    for (int it = 0; it < 5; it++) {
        ns_mm<<<dim3(2, 4, 16), blk>>>(p_Weps, Xc, p_T, 1);   // T = 2I - Weps@X
        ns_mm<<<dim3(2, 4, 16), blk>>>(Xc, p_T, Xn, 0);       // X = X@T
        float* t = Xc; Xc = Xn; Xn = t;
    }
    // result in g_Xb

    // 4. C_q / C_k
    lap_kernel<<<dim3(16, 2, 16), blk, 4 * 64 * 66 * 4>>>(tm);

    // 5. whitening stats
    stats_part<<<dim3(16, 8), 128>>>(tm);
    stats_fin<<<4, 256>>>();

    // 6. context = W_inv @ (Ck^T @ v)
    ckv_part_kernel<<<dim3(8, 16), blk, 98304>>>();
    ctx_kernel<<<16, blk, 98304>>>();

    // 7. ga + depthwise local term
    ga_kernel<<<dim3(8, 16), blk, 98304>>>(tm);
    vlocal_kernel<<<4096, 256>>>(tm, dwc_w, dwc_b);

    // 8. output projection
    gemm_bias_mask<<<dim3(512 / 64, 2048 / 128), blk>>>(p_gab, proj_w, proj_b, tm, out,
                                                        Bn * Nn, Cc, Cc);
}

// round 9
// speedup vs baseline: 1.5966x; 1.5966x over previous
#include <cuda_runtime.h>
#include <math.h>

constexpr int Bn = 2, Nn = 1024, Cc = 512, Hc = 8, Dc = 64, Mc = 128, BHc = 16;

// ---------------- scratch ----------------------------------------------------
__device__ float g_qkv [Bn*Nn*3*Cc];
__device__ float g_pms [Bn*Mc];
__device__ float g_lmask[Bn*Mc];
__device__ float g_valid[1];
__device__ float g_fro [BHc];
__device__ float g_ql  [BHc*Mc*Dc];
__device__ float g_kl  [BHc*Mc*Dc];
__device__ float g_Weps[BHc*Mc*Mc];
__device__ float g_Xa  [BHc*Mc*Mc];
__device__ float g_Xb  [BHc*Mc*Mc];
__device__ float g_T   [BHc*Mc*Mc];
__device__ float g_Cq  [BHc*Nn*Mc];
__device__ float g_Ck  [BHc*Nn*Mc];
__device__ float g_stats[4*Hc*Mc];
__device__ float g_mu  [Hc*Mc];
__device__ float g_rstd[Hc*Mc];
__device__ float g_ckvp[BHc*8*Mc*Dc];
__device__ float g_ctx [BHc*Mc*Dc];
__device__ float g_gab [Bn*Nn*Cc];

// ---------------- f32x2 helpers ---------------------------------------------
typedef unsigned long long ull;
__device__ __forceinline__ void ffma2(ull& d, ull a, ull b) {
    asm("fma.rn.f32x2 %0, %1, %2, %0;" : "+l"(d) : "l"(a), "l"(b));
}
__device__ __forceinline__ ull dup2(float x) {
    ull u; asm("mov.b64 %0,{%1,%2};" : "=l"(u) : "f"(x), "f"(x)); return u;
}
__device__ __forceinline__ float2 unpack2(ull u) {
    float2 v; asm("mov.b64 {%0,%1},%2;" : "=f"(v.x), "=f"(v.y) : "l"(u)); return v;
}

// ---------------- GEMM: out = (A @ W^T + bias) * tm[row] ---------------------
// 128x64 tile, 16x16 threads. f32x2 pairs on the ROW axis: thread owns row
// pairs (32a+2ty, +1), a<4, and 4 scalar cols tx+16c. A pair loads are natural
// LDS.64 (no dup); only the 4 B scalars get dup'd per kk.
__global__ __launch_bounds__(256) void gemm_bias_mask(
        const float* __restrict__ A, const float* __restrict__ W,
        const float* __restrict__ bias, const float* __restrict__ tm,
        float* __restrict__ out, int M, int Nout, int K)
{
    __shared__ float As[16 * 130];
    __shared__ float Bs[16 * 66];
    int tx = threadIdx.x, ty = threadIdx.y;
    int tid = ty * 16 + tx;
    int rb = blockIdx.y * 128, cb = blockIdx.x * 64;
    ull acc[4][4] = {};
    for (int k0 = 0; k0 < K; k0 += 16) {
#pragma unroll
        for (int l = 0; l < 8; l++) {
            int e = tid + l * 256;
            int r = e >> 4, kk = e & 15;
            As[kk * 130 + r] = A[(rb + r) * K + k0 + kk];
        }
#pragma unroll
        for (int l = 0; l < 4; l++) {
            int e = tid + l * 256;
            int r = e >> 4, kk = e & 15;
            Bs[kk * 66 + r] = W[(cb + r) * K + k0 + kk];
        }
        __syncthreads();
#pragma unroll
        for (int kk = 0; kk < 16; kk++) {
            ull av[4];
#pragma unroll
            for (int a = 0; a < 4; a++)
                av[a] = *(const ull*)&As[kk * 130 + 32 * a + 2 * ty];
            ull bd[4];
#pragma unroll
            for (int c = 0; c < 4; c++)
                bd[c] = dup2(Bs[kk * 66 + tx + 16 * c]);
#pragma unroll
            for (int a = 0; a < 4; a++)
#pragma unroll
                for (int c = 0; c < 4; c++)
                    ffma2(acc[a][c], av[a], bd[c]);
        }
        __syncthreads();
    }
#pragma unroll
    for (int a = 0; a < 4; a++) {
        int r0 = rb + 32 * a + 2 * ty;
        float t0 = tm[r0], t1 = tm[r0 + 1];
#pragma unroll
        for (int c = 0; c < 4; c++) {
            int j = cb + tx + 16 * c;
            float bi = bias[j];
            float2 v = unpack2(acc[a][c]);
            out[r0 * Nout + j]       = (v.x + bi) * t0;
            out[(r0 + 1) * Nout + j] = (v.y + bi) * t1;
        }
    }
}

// ---------------- batched NS matmul: 32x64 tiles, f32x2 ----------------------
// mode 0: Out = A@B ; mode 1: Out = 2I - A@B
__global__ __launch_bounds__(256) void ns_mm(
        const float* __restrict__ A, const float* __restrict__ Bm,
        float* __restrict__ Out, int mode)
{
    __shared__ float As[16 * 33];
    __shared__ float Bs[16 * 66];
    int tx = threadIdx.x, ty = threadIdx.y;
    int tid = ty * 16 + tx;
    int batch = blockIdx.z;
    const float* Ab = A + batch * Mc * Mc;
    const float* Bb = Bm + batch * Mc * Mc;
    float* Ob = Out + batch * Mc * Mc;
    int rb = blockIdx.y * 32, cb = blockIdx.x * 64;
    ull acc[2][2] = {};
    for (int k0 = 0; k0 < 128; k0 += 16) {
#pragma unroll
        for (int l = 0; l < 2; l++) {
            int e = tid + l * 256;
            int r = e >> 4, kk = e & 15;
            As[kk * 33 + r] = Ab[(rb + r) * 128 + k0 + kk];
        }
#pragma unroll
        for (int l = 0; l < 4; l++) {
            int e = tid + l * 256;
            int kb = e >> 6, j = e & 63;
            Bs[kb * 66 + j] = Bb[(k0 + kb) * 128 + cb + j];
        }
        __syncthreads();
#pragma unroll
        for (int kk = 0; kk < 16; kk++) {
            ull a0 = dup2(As[kk * 33 + ty]);
            ull a1 = dup2(As[kk * 33 + ty + 16]);
            ull b0 = *(const ull*)&Bs[kk * 66 + 2 * tx];
            ull b1 = *(const ull*)&Bs[kk * 66 + 2 * tx + 32];
            ffma2(acc[0][0], a0, b0);
            ffma2(acc[0][1], a0, b1);
            ffma2(acc[1][0], a1, b0);
            ffma2(acc[1][1], a1, b1);
        }
        __syncthreads();
    }
#pragma unroll
    for (int a = 0; a < 2; a++) {
        int i = rb + ty + 16 * a;
#pragma unroll
        for (int c = 0; c < 2; c++) {
            int j0 = cb + 2 * tx + 32 * c;
            float2 v = unpack2(acc[a][c]);
            if (mode) {
                v.x = ((i == j0)     ? 2.f : 0.f) - v.x;
                v.y = ((i == j0 + 1) ? 2.f : 0.f) - v.y;
            }
            *(float2*)&Ob[i * 128 + j0] = v;
        }
    }
}

// ---------------- pooled-mask stats (+ zero g_stats, g_fro) ------------------
__global__ void pm_kernel(const float* __restrict__ tm)
{
    __shared__ float red[256];
    int t = threadIdx.x;
    int b = t >> 7, mm = t & 127;
    if (t < BHc) g_fro[t] = 0.f;
    for (int e = t; e < 4 * Hc * Mc; e += 256) g_stats[e] = 0.f;
    float s = 0.f;
#pragma unroll
    for (int j = 0; j < 8; j++) s += tm[b * Nn + mm * 8 + j];
    float pm = s * 0.125f;
    g_pms[t] = fmaxf(pm, 1e-6f);
    g_lmask[t] = pm > 0.f ? 1.f : 0.f;
    red[t] = s;
    __syncthreads();
    for (int o = 128; o > 0; o >>= 1) {
        if (t < o) red[t] += red[t + o];
        __syncthreads();
    }
    if (t == 0) g_valid[0] = fmaxf(red[0], 1.f);
}

// ---------------- pooled q_l / k_l: coalesced float4 loads -------------------
__global__ void pool_kernel(const float* __restrict__ tm)
{
    int i = blockIdx.x * 256 + threadIdx.x;
    int mm = i & 127;
    int d  = (i >> 7) & 63;
    int h  = (i >> 13) & 7;
    int b  = (i >> 16) & 1;
    int s  = i >> 17;
    int c = h * 64 + d;
    int f0 = c * 1024 + mm * 8;
    int n = f0 >> 9, hd = f0 & 511;
    const float4* p = (const float4*)&g_qkv[(b * Nn + n) * 1536 + s * 512 + hd];
    float4 v0 = p[0], v1 = p[1];
    const float4* tp = (const float4*)&tm[b * Nn + mm * 8];
    float4 t0 = tp[0], t1 = tp[1];
    float acc = v0.x * t0.x + v0.y * t0.y + v0.z * t0.z + v0.w * t0.w
              + v1.x * t1.x + v1.y * t1.y + v1.z * t1.z + v1.w * t1.w;
    acc = acc * 0.125f / g_pms[b * 128 + mm];
    float* dst = (s == 0) ? g_ql : g_kl;
    dst[((b * 8 + h) * 128 + mm) * 64 + d] = acc;
}

// ---------------- W_eps: 32x32 tiles, grid (4,4,16) --------------------------
__global__ __launch_bounds__(256) void buildW_A()
{
    __shared__ float sql[32 * 65];
    __shared__ float skl[32 * 65];
    int tx = threadIdx.x, ty = threadIdx.y;
    int tid = ty * 16 + tx;
    int batch = blockIdx.z;
    int b = batch >> 3;
    int rb = blockIdx.y * 32, cb = blockIdx.x * 32;
    for (int e = tid; e < 2048; e += 256) {
        int r = e >> 6, d = e & 63;
        sql[r * 65 + d] = g_ql[batch * 8192 + (rb + r) * 64 + d];
        skl[r * 65 + d] = g_kl[batch * 8192 + (cb + r) * 64 + d];
    }
    __syncthreads();
    float acc[2][2] = {};
    for (int d = 0; d < 64; d++) {
        float q0 = sql[ty * 65 + d], q1 = sql[(ty + 16) * 65 + d];
        float k0 = skl[tx * 65 + d], k1 = skl[(tx + 16) * 65 + d];
        acc[0][0] += fabsf(q0 - k0);
        acc[0][1] += fabsf(q0 - k1);
        acc[1][0] += fabsf(q1 - k0);
        acc[1][1] += fabsf(q1 - k1);
    }
    float fro = 0.f;
#pragma unroll
    for (int a = 0; a < 2; a++)
#pragma unroll
        for (int bb = 0; bb < 2; bb++) {
            int i = rb + ty + 16 * a;
            int j = cb + tx + 16 * bb;
            float w = __expf(-acc[a][bb] * 0.25f);
            float pair = g_lmask[b * 128 + i] * g_lmask[b * 128 + j];
            float diag = (i == j) ? 1.f : 0.f;
            w = w * pair + diag * (1.f - pair) + diag * 1e-4f;
            g_Weps[batch * 16384 + i * 128 + j] = w;
            fro += w * w;
        }
#pragma unroll
    for (int o = 16; o > 0; o >>= 1)
        fro += __shfl_xor_sync(0xffffffffu, fro, o);
    if ((tid & 31) == 0) atomicAdd(&g_fro[batch], fro);
}

// X0 = (2/(||Weps||_F + 1e-8)) * Weps^T
__global__ void buildW_B()
{
    int batch = blockIdx.x;
    int tid = threadIdx.x;
    float s = 2.f / (sqrtf(g_fro[batch]) + 1e-8f);
    for (int e = tid; e < 16384; e += 256) {
        int i = e >> 7, j = e & 127;
        g_Xa[batch * 16384 + j * 128 + i] = s * g_Weps[batch * 16384 + e];
    }
}

// ---------------- C_q / C_k laplacian kernels --------------------------------
__global__ void lap_kernel(const float* __restrict__ tm)
{
    extern __shared__ float sh[];
    float* sql = sh;
    float* skl = sql + 128 * 65;
    float* sq  = skl + 128 * 65;
    float* sk  = sq + 64 * 65;
    int tx = threadIdx.x, ty = threadIdx.y;
    int tid = ty * 16 + tx;
    int batch = blockIdx.y;
    int b = batch >> 3, h = batch & 7;
    int n0 = blockIdx.x * 64;
    for (int e = tid; e < 8192; e += 256) {
        int r = e >> 6, d = e & 63;
        sql[r * 65 + d] = g_ql[batch * 8192 + e];
        skl[r * 65 + d] = g_kl[batch * 8192 + e];
    }
    for (int e = tid; e < 4096; e += 256) {
        int r = e >> 6, d = e & 63;
        const float* row = &g_qkv[(b * Nn + n0 + r) * 1536 + h * 64];
        sq[r * 65 + d] = row[d];
        sk[r * 65 + d] = row[512 + d];
    }
    __syncthreads();
    float accq[4][8] = {}, acck[4][8] = {};
    for (int d = 0; d < 64; d++) {
        float qf[4], kf[4], qlf[8], klf[8];
#pragma unroll
        for (int a = 0; a < 4; a++) {
            qf[a] = sq[(ty + 16 * a) * 65 + d];
            kf[a] = sk[(ty + 16 * a) * 65 + d];
        }
#pragma unroll
        for (int bb = 0; bb < 8; bb++) {
            qlf[bb] = sql[(tx + 16 * bb) * 65 + d];
            klf[bb] = skl[(tx + 16 * bb) * 65 + d];
        }
#pragma unroll
        for (int a = 0; a < 4; a++)
#pragma unroll
            for (int bb = 0; bb < 8; bb++) {
                accq[a][bb] += fabsf(qf[a] - klf[bb]);
                acck[a][bb] += fabsf(kf[a] - qlf[bb]);
            }
    }
#pragma unroll
    for (int a = 0; a < 4; a++)
#pragma unroll
        for (int bb = 0; bb < 8; bb++) {
            int n = n0 + ty + 16 * a;
            int j = tx + 16 * bb;
            float lm = g_lmask[b * 128 + j];
            g_Cq[(batch * Nn + n) * 128 + j] = __expf(-accq[a][bb] * 0.25f) * lm;
            g_Ck[(batch * Nn + n) * 128 + j] = __expf(-acck[a][bb] * 0.25f) * lm;
        }
}

// ---------------- whitening stats --------------------------------------------
__global__ void stats_part(const float* __restrict__ tm)
{
    int h = blockIdx.y;
    int s = blockIdx.x;
    int j = threadIdx.x;
    float a1 = 0.f, b0 = 0.f, b1 = 0.f, b2 = 0.f;
    for (int r = 0; r < 128; r++) {
        int row = s * 128 + r;
        int b = row >> 10, n = row & 1023;
        float t = tm[row];
        float c = g_Cq[((b * 8 + h) * Nn + n) * 128 + j];
        float tc = t * c;
        a1 += tc;
        b0 += t * t;
        b1 += t * tc;
        b2 += tc * tc;
    }
    atomicAdd(&g_stats[0 * 1024 + h * 128 + j], a1);
    atomicAdd(&g_stats[1 * 1024 + h * 128 + j], b0);
    atomicAdd(&g_stats[2 * 1024 + h * 128 + j], b1);
    atomicAdd(&g_stats[3 * 1024 + h * 128 + j], b2);
}

__global__ void stats_fin()
{
    int i = blockIdx.x * 256 + threadIdx.x;
    if (i >= Hc * Mc) return;
    float valid = g_valid[0];
    float a1 = g_stats[i], b0 = g_stats[1024 + i], b1 = g_stats[2048 + i], b2 = g_stats[3072 + i];
    float mu = a1 / valid;
    float var = (b2 - 2.f * mu * b1 + mu * mu * b0) / valid;
    g_mu[i] = mu;
    g_rstd[i] = 1.f / sqrtf(var + 1e-5f);
}

// ---------------- ckv partials (f32x2 along d) -------------------------------
__global__ void ckv_part_kernel()
{
    extern __shared__ float sh[];
    float* sCk = sh;
    float* sV  = sh + 16384;
    int tx = threadIdx.x, ty = threadIdx.y;
    int tid = ty * 16 + tx;
    int batch = blockIdx.y, split = blockIdx.x;
    int b = batch >> 3, h = batch & 7;
    int n0 = split * 128;
    for (int e = tid; e < 16384; e += 256)
        sCk[e] = g_Ck[(batch * Nn + n0 + (e >> 7)) * 128 + (e & 127)];
    for (int e = tid; e < 8192; e += 256)
        sV[e] = g_qkv[(b * Nn + n0 + (e >> 6)) * 1536 + 1024 + h * 64 + (e & 63)];
    __syncthreads();
    ull acc[8][2] = {};
    for (int n = 0; n < 128; n++) {
        ull cd[8];
#pragma unroll
        for (int a = 0; a < 8; a++) cd[a] = dup2(sCk[n * 128 + ty + 16 * a]);
        ull v0 = *(const ull*)&sV[n * 64 + 2 * tx];
        ull v1 = *(const ull*)&sV[n * 64 + 2 * tx + 32];
#pragma unroll
        for (int a = 0; a < 8; a++) {
            ffma2(acc[a][0], cd[a], v0);
            ffma2(acc[a][1], cd[a], v1);
        }
    }
#pragma unroll
    for (int a = 0; a < 8; a++) {
        int j = ty + 16 * a;
        float* dst = &g_ckvp[((batch * 8 + split) * 128 + j) * 64];
        *(float2*)&dst[2 * tx]      = unpack2(acc[a][0]);
        *(float2*)&dst[2 * tx + 32] = unpack2(acc[a][1]);
    }
}

// ---------------- context = W_inv @ ckv --------------------------------------
__global__ void ctx_kernel()
{
    extern __shared__ float sh[];
    float* sW = sh;
    float* sC = sh + 16384;
    int tx = threadIdx.x, ty = threadIdx.y;
    int tid = ty * 16 + tx;
    int batch = blockIdx.x;
    for (int e = tid; e < 16384; e += 256)
        sW[e] = g_Xb[batch * 16384 + e];
    for (int e = tid; e < 8192; e += 256) {
        float s = 0.f;
#pragma unroll
        for (int p = 0; p < 8; p++) s += g_ckvp[(batch * 8 + p) * 8192 + e];
        sC[e] = s;
    }
    __syncthreads();
    ull acc[8][2] = {};
    for (int j = 0; j < 128; j++) {
        ull wd[8];
#pragma unroll
        for (int a = 0; a < 8; a++) wd[a] = dup2(sW[(ty + 16 * a) * 128 + j]);
        ull c0 = *(const ull*)&sC[j * 64 + 2 * tx];
        ull c1 = *(const ull*)&sC[j * 64 + 2 * tx + 32];
#pragma unroll
        for (int a = 0; a < 8; a++) {
            ffma2(acc[a][0], wd[a], c0);
            ffma2(acc[a][1], wd[a], c1);
        }
    }
#pragma unroll
    for (int a = 0; a < 8; a++) {
        float* dst = &g_ctx[batch * 8192 + (ty + 16 * a) * 64];
        *(float2*)&dst[2 * tx]      = unpack2(acc[a][0]);
        *(float2*)&dst[2 * tx + 32] = unpack2(acc[a][1]);
    }
}

// ---------------- ga = (C_q_norm @ context) * mh -----------------------------
__global__ void ga_kernel(const float* __restrict__ tm)
{
    extern __shared__ float sh[];
    float* sCq = sh;
    float* sC  = sh + 16384;
    int tx = threadIdx.x, ty = threadIdx.y;
    int tid = ty * 16 + tx;
    int batch = blockIdx.y, nt = blockIdx.x;
    int b = batch >> 3, h = batch & 7;
    int n0 = nt * 128;
    for (int e = tid; e < 16384; e += 256) {
        int nl = e >> 7, j = e & 127;
        float t = tm[b * Nn + n0 + nl];
        sCq[e] = (g_Cq[(batch * Nn + n0 + nl) * 128 + j] - g_mu[h * 128 + j]) * g_rstd[h * 128 + j] * t;
    }
    for (int e = tid; e < 8192; e += 256)
        sC[e] = g_ctx[batch * 8192 + e];
    __syncthreads();
    ull acc[8][2] = {};
    for (int j = 0; j < 128; j++) {
        ull qd[8];
#pragma unroll
        for (int a = 0; a < 8; a++) qd[a] = dup2(sCq[(ty + 16 * a) * 128 + j]);
        ull c0 = *(const ull*)&sC[j * 64 + 2 * tx];
        ull c1 = *(const ull*)&sC[j * 64 + 2 * tx + 32];
#pragma unroll
        for (int a = 0; a < 8; a++) {
            ffma2(acc[a][0], qd[a], c0);
            ffma2(acc[a][1], qd[a], c1);
        }
    }
#pragma unroll
    for (int a = 0; a < 8; a++) {
        int n = n0 + ty + 16 * a;
        float t = tm[b * Nn + n];
        float2 v0 = unpack2(acc[a][0]);
        float2 v1 = unpack2(acc[a][1]);
        v0.x *= t; v0.y *= t; v1.x *= t; v1.y *= t;
        float* dst = &g_gab[(b * Nn + n) * 512 + h * 64];
        *(float2*)&dst[2 * tx]      = v0;
        *(float2*)&dst[2 * tx + 32] = v1;
    }
}

// ---------------- depthwise "conv" on the scrambled flat view ----------------
__global__ void vlocal_kernel(const float* __restrict__ tm, const float* __restrict__ dw,
                              const float* __restrict__ db)
{
    int i = blockIdx.x * 256 + threadIdx.x;
    int n2 = i & 1023;
    int ch = (i >> 10) & 511;
    int b  = i >> 19;
    float w0 = dw[ch * 3 + 0], w1 = dw[ch * 3 + 1], w2 = dw[ch * 3 + 2];
    int f = ch * 1024 + n2;
    float acc = db[ch];
    if (n2 > 0) {
        int ff = f - 1;
        acc += w0 * g_qkv[(b * Nn + (ff >> 9)) * 1536 + 1024 + (ff & 511)];
    }
    acc += w1 * g_qkv[(b * Nn + (f >> 9)) * 1536 + 1024 + (f & 511)];
    if (n2 < 1023) {
        int ff = f + 1;
        acc += w2 * g_qkv[(b * Nn + (ff >> 9)) * 1536 + 1024 + (ff & 511)];
    }
    g_gab[(b * Nn + n2) * 512 + ch] += acc * tm[b * Nn + n2];
}

// ---------------- launch -----------------------------------------------------
extern "C" void kernel_launch(void* const* d_in, const int* in_sizes, int n_in,
                              void* d_out, int out_size)
{
    const float* x      = (const float*)d_in[0];
    const float* tm     = (const float*)d_in[1];
    const float* qkv_w  = (const float*)d_in[2];
    const float* qkv_b  = (const float*)d_in[3];
    const float* proj_w = (const float*)d_in[4];
    const float* proj_b = (const float*)d_in[5];
    const float* dwc_w  = (const float*)d_in[6];
    const float* dwc_b  = (const float*)d_in[7];
    float* out = (float*)d_out;

    float *p_qkv, *p_gab, *p_Weps, *p_Xa, *p_Xb, *p_T;
    cudaGetSymbolAddress((void**)&p_qkv,  g_qkv);
    cudaGetSymbolAddress((void**)&p_gab,  g_gab);
    cudaGetSymbolAddress((void**)&p_Weps, g_Weps);
    cudaGetSymbolAddress((void**)&p_Xa,   g_Xa);
    cudaGetSymbolAddress((void**)&p_Xb,   g_Xb);
    cudaGetSymbolAddress((void**)&p_T,    g_T);

    cudaFuncSetAttribute(lap_kernel,      cudaFuncAttributeMaxDynamicSharedMemorySize, 99840);
    cudaFuncSetAttribute(ckv_part_kernel, cudaFuncAttributeMaxDynamicSharedMemorySize, 98304);
    cudaFuncSetAttribute(ctx_kernel,      cudaFuncAttributeMaxDynamicSharedMemorySize, 98304);
    cudaFuncSetAttribute(ga_kernel,       cudaFuncAttributeMaxDynamicSharedMemorySize, 98304);

    dim3 blk(16, 16);

    // 1. masked QKV projection (128x64 tiles)
    gemm_bias_mask<<<dim3(1536 / 64, 2048 / 128), blk>>>(x, qkv_w, qkv_b, tm, p_qkv,
                                                         Bn * Nn, 3 * Cc, Cc);
    // 2. pooled-mask stats + pooled q_l/k_l
    pm_kernel<<<1, 256>>>(tm);
    pool_kernel<<<1024, 256>>>(tm);

    // 3. W_eps + X0, Newton-Schulz (5 iters)
    buildW_A<<<dim3(4, 4, 16), blk>>>();
    buildW_B<<<16, 256>>>();
    float* Xc = p_Xa;
    float* Xn = p_Xb;
    for (int it = 0; it < 5; it++) {
        ns_mm<<<dim3(2, 4, 16), blk>>>(p_Weps, Xc, p_T, 1);   // T = 2I - Weps@X
        ns_mm<<<dim3(2, 4, 16), blk>>>(Xc, p_T, Xn, 0);       // X = X@T
        float* t = Xc; Xc = Xn; Xn = t;
    }
    // result in g_Xb

    // 4. C_q / C_k
    lap_kernel<<<dim3(16, 16), blk, 99840>>>(tm);

    // 5. whitening stats
    stats_part<<<dim3(16, 8), 128>>>(tm);
    stats_fin<<<4, 256>>>();

    // 6. context = W_inv @ (Ck^T @ v)
    ckv_part_kernel<<<dim3(8, 16), blk, 98304>>>();
    ctx_kernel<<<16, blk, 98304>>>();

    // 7. ga + depthwise local term
    ga_kernel<<<dim3(8, 16), blk, 98304>>>(tm);
    vlocal_kernel<<<4096, 256>>>(tm, dwc_w, dwc_b);

    // 8. output projection
    gemm_bias_mask<<<dim3(512 / 64, 2048 / 128), blk>>>(p_gab, proj_w, proj_b, tm, out,
                                                        Bn * Nn, Cc, Cc);
}

// round 10
// speedup vs baseline: 1.7819x; 1.1160x over previous
#include <cuda_runtime.h>
#include <math.h>

constexpr int Bn = 2, Nn = 1024, Cc = 512, Hc = 8, Dc = 64, Mc = 128, BHc = 16;

// ---------------- scratch ----------------------------------------------------
__device__ float g_qkv [Bn*Nn*3*Cc];
__device__ float g_pms [Bn*Mc];
__device__ float g_lmask[Bn*Mc];
__device__ float g_valid[1];
__device__ float g_fro [BHc];
__device__ float g_ql  [BHc*Mc*Dc];
__device__ float g_kl  [BHc*Mc*Dc];
__device__ float g_Weps[BHc*Mc*Mc];
__device__ float g_Xa  [BHc*Mc*Mc];
__device__ float g_Xb  [BHc*Mc*Mc];
__device__ float g_T   [BHc*Mc*Mc];
__device__ float g_Cq  [BHc*Nn*Mc];
__device__ float g_Ck  [BHc*Nn*Mc];
__device__ float g_stats[4*Hc*Mc];
__device__ float g_mu  [Hc*Mc];
__device__ float g_rstd[Hc*Mc];
__device__ float g_ckvp[BHc*8*Mc*Dc];
__device__ float g_ctx [BHc*Mc*Dc];
__device__ float g_gab [Bn*Nn*Cc];

// ---------------- f32x2 helpers ---------------------------------------------
typedef unsigned long long ull;
__device__ __forceinline__ void ffma2(ull& d, ull a, ull b) {
    asm("fma.rn.f32x2 %0, %1, %2, %0;" : "+l"(d) : "l"(a), "l"(b));
}
__device__ __forceinline__ ull dup2(float x) {
    ull u; asm("mov.b64 %0,{%1,%2};" : "=l"(u) : "f"(x), "f"(x)); return u;
}
__device__ __forceinline__ float2 unpack2(ull u) {
    float2 v; asm("mov.b64 {%0,%1},%2;" : "=f"(v.x), "=f"(v.y) : "l"(u)); return v;
}

// ---------------- GEMM: out = (A @ W^T + bias) * tm[row] ---------------------
// 128x64 tile, 16x16 threads, f32x2 pairs on the ROW axis. SOFTWARE PIPELINED:
// next k-tile is prefetched global->regs during the FFMA2 block.
__global__ __launch_bounds__(256) void gemm_bias_mask(
        const float* __restrict__ A, const float* __restrict__ W,
        const float* __restrict__ bias, const float* __restrict__ tm,
        float* __restrict__ out, int M, int Nout, int K)
{
    __shared__ float As[16 * 130];
    __shared__ float Bs[16 * 66];
    int tx = threadIdx.x, ty = threadIdx.y;
    int tid = ty * 16 + tx;
    int rb = blockIdx.y * 128, cb = blockIdx.x * 64;
    ull acc[4][4] = {};
    float ra[8], rbw[4];
    // prologue: load k-tile 0
#pragma unroll
    for (int l = 0; l < 8; l++) {
        int e = tid + l * 256;
        ra[l] = A[(rb + (e >> 4)) * K + (e & 15)];
    }
#pragma unroll
    for (int l = 0; l < 4; l++) {
        int e = tid + l * 256;
        rbw[l] = W[(cb + (e >> 4)) * K + (e & 15)];
    }
    for (int k0 = 0; k0 < K; k0 += 16) {
#pragma unroll
        for (int l = 0; l < 8; l++) {
            int e = tid + l * 256;
            As[(e & 15) * 130 + (e >> 4)] = ra[l];
        }
#pragma unroll
        for (int l = 0; l < 4; l++) {
            int e = tid + l * 256;
            Bs[(e & 15) * 66 + (e >> 4)] = rbw[l];
        }
        __syncthreads();
        if (k0 + 16 < K) {
#pragma unroll
            for (int l = 0; l < 8; l++) {
                int e = tid + l * 256;
                ra[l] = A[(rb + (e >> 4)) * K + k0 + 16 + (e & 15)];
            }
#pragma unroll
            for (int l = 0; l < 4; l++) {
                int e = tid + l * 256;
                rbw[l] = W[(cb + (e >> 4)) * K + k0 + 16 + (e & 15)];
            }
        }
#pragma unroll
        for (int kk = 0; kk < 16; kk++) {
            ull av[4];
#pragma unroll
            for (int a = 0; a < 4; a++)
                av[a] = *(const ull*)&As[kk * 130 + 32 * a + 2 * ty];
            ull bd[4];
#pragma unroll
            for (int c = 0; c < 4; c++)
                bd[c] = dup2(Bs[kk * 66 + tx + 16 * c]);
#pragma unroll
            for (int a = 0; a < 4; a++)
#pragma unroll
                for (int c = 0; c < 4; c++)
                    ffma2(acc[a][c], av[a], bd[c]);
        }
        __syncthreads();
    }
#pragma unroll
    for (int a = 0; a < 4; a++) {
        int r0 = rb + 32 * a + 2 * ty;
        float t0 = tm[r0], t1 = tm[r0 + 1];
#pragma unroll
        for (int c = 0; c < 4; c++) {
            int j = cb + tx + 16 * c;
            float bi = bias[j];
            float2 v = unpack2(acc[a][c]);
            out[r0 * Nout + j]       = (v.x + bi) * t0;
            out[(r0 + 1) * Nout + j] = (v.y + bi) * t1;
        }
    }
}

// ---------------- batched NS matmul: 32x64 tiles, f32x2, pipelined -----------
// mode 0: Out = A@B ; mode 1: Out = 2I - A@B
__global__ __launch_bounds__(256) void ns_mm(
        const float* __restrict__ A, const float* __restrict__ Bm,
        float* __restrict__ Out, int mode)
{
    __shared__ float As[16 * 33];
    __shared__ float Bs[16 * 66];
    int tx = threadIdx.x, ty = threadIdx.y;
    int tid = ty * 16 + tx;
    int batch = blockIdx.z;
    const float* Ab = A + batch * Mc * Mc;
    const float* Bb = Bm + batch * Mc * Mc;
    float* Ob = Out + batch * Mc * Mc;
    int rb = blockIdx.y * 32, cb = blockIdx.x * 64;
    ull acc[2][2] = {};
    float ra[2], rbw[4];
#pragma unroll
    for (int l = 0; l < 2; l++) {
        int e = tid + l * 256;
        ra[l] = Ab[(rb + (e >> 4)) * 128 + (e & 15)];
    }
#pragma unroll
    for (int l = 0; l < 4; l++) {
        int e = tid + l * 256;
        rbw[l] = Bb[(e >> 6) * 128 + cb + (e & 63)];
    }
    for (int k0 = 0; k0 < 128; k0 += 16) {
#pragma unroll
        for (int l = 0; l < 2; l++) {
            int e = tid + l * 256;
            As[(e & 15) * 33 + (e >> 4)] = ra[l];
        }
#pragma unroll
        for (int l = 0; l < 4; l++) {
            int e = tid + l * 256;
            Bs[(e >> 6) * 66 + (e & 63)] = rbw[l];
        }
        __syncthreads();
        if (k0 + 16 < 128) {
#pragma unroll
            for (int l = 0; l < 2; l++) {
                int e = tid + l * 256;
                ra[l] = Ab[(rb + (e >> 4)) * 128 + k0 + 16 + (e & 15)];
            }
#pragma unroll
            for (int l = 0; l < 4; l++) {
                int e = tid + l * 256;
                rbw[l] = Bb[(k0 + 16 + (e >> 6)) * 128 + cb + (e & 63)];
            }
        }
#pragma unroll
        for (int kk = 0; kk < 16; kk++) {
            ull a0 = dup2(As[kk * 33 + ty]);
            ull a1 = dup2(As[kk * 33 + ty + 16]);
            ull b0 = *(const ull*)&Bs[kk * 66 + 2 * tx];
            ull b1 = *(const ull*)&Bs[kk * 66 + 2 * tx + 32];
            ffma2(acc[0][0], a0, b0);
            ffma2(acc[0][1], a0, b1);
            ffma2(acc[1][0], a1, b0);
            ffma2(acc[1][1], a1, b1);
        }
        __syncthreads();
    }
#pragma unroll
    for (int a = 0; a < 2; a++) {
        int i = rb + ty + 16 * a;
#pragma unroll
        for (int c = 0; c < 2; c++) {
            int j0 = cb + 2 * tx + 32 * c;
            float2 v = unpack2(acc[a][c]);
            if (mode) {
                v.x = ((i == j0)     ? 2.f : 0.f) - v.x;
                v.y = ((i == j0 + 1) ? 2.f : 0.f) - v.y;
            }
            *(float2*)&Ob[i * 128 + j0] = v;
        }
    }
}

// ---------------- pooled-mask stats (+ zero g_stats, g_fro) ------------------
__global__ void pm_kernel(const float* __restrict__ tm)
{
    __shared__ float red[256];
    int t = threadIdx.x;
    int b = t >> 7, mm = t & 127;
    if (t < BHc) g_fro[t] = 0.f;
    for (int e = t; e < 4 * Hc * Mc; e += 256) g_stats[e] = 0.f;
    float s = 0.f;
#pragma unroll
    for (int j = 0; j < 8; j++) s += tm[b * Nn + mm * 8 + j];
    float pm = s * 0.125f;
    g_pms[t] = fmaxf(pm, 1e-6f);
    g_lmask[t] = pm > 0.f ? 1.f : 0.f;
    red[t] = s;
    __syncthreads();
    for (int o = 128; o > 0; o >>= 1) {
        if (t < o) red[t] += red[t + o];
        __syncthreads();
    }
    if (t == 0) g_valid[0] = fmaxf(red[0], 1.f);
}

// ---------------- pooled q_l / k_l: coalesced float4 loads -------------------
__global__ void pool_kernel(const float* __restrict__ tm)
{
    int i = blockIdx.x * 256 + threadIdx.x;
    int mm = i & 127;
    int d  = (i >> 7) & 63;
    int h  = (i >> 13) & 7;
    int b  = (i >> 16) & 1;
    int s  = i >> 17;
    int c = h * 64 + d;
    int f0 = c * 1024 + mm * 8;
    int n = f0 >> 9, hd = f0 & 511;
    const float4* p = (const float4*)&g_qkv[(b * Nn + n) * 1536 + s * 512 + hd];
    float4 v0 = p[0], v1 = p[1];
    const float4* tp = (const float4*)&tm[b * Nn + mm * 8];
    float4 t0 = tp[0], t1 = tp[1];
    float acc = v0.x * t0.x + v0.y * t0.y + v0.z * t0.z + v0.w * t0.w
              + v1.x * t1.x + v1.y * t1.y + v1.z * t1.z + v1.w * t1.w;
    acc = acc * 0.125f / g_pms[b * 128 + mm];
    float* dst = (s == 0) ? g_ql : g_kl;
    dst[((b * 8 + h) * 128 + mm) * 64 + d] = acc;
}

// ---------------- W_eps: 32x32 tiles, grid (4,4,16) --------------------------
__global__ __launch_bounds__(256) void buildW_A()
{
    __shared__ float sql[32 * 65];
    __shared__ float skl[32 * 65];
    int tx = threadIdx.x, ty = threadIdx.y;
    int tid = ty * 16 + tx;
    int batch = blockIdx.z;
    int b = batch >> 3;
    int rb = blockIdx.y * 32, cb = blockIdx.x * 32;
    for (int e = tid; e < 2048; e += 256) {
        int r = e >> 6, d = e & 63;
        sql[r * 65 + d] = g_ql[batch * 8192 + (rb + r) * 64 + d];
        skl[r * 65 + d] = g_kl[batch * 8192 + (cb + r) * 64 + d];
    }
    __syncthreads();
    float acc[2][2] = {};
    for (int d = 0; d < 64; d++) {
        float q0 = sql[ty * 65 + d], q1 = sql[(ty + 16) * 65 + d];
        float k0 = skl[tx * 65 + d], k1 = skl[(tx + 16) * 65 + d];
        acc[0][0] += fabsf(q0 - k0);
        acc[0][1] += fabsf(q0 - k1);
        acc[1][0] += fabsf(q1 - k0);
        acc[1][1] += fabsf(q1 - k1);
    }
    float fro = 0.f;
#pragma unroll
    for (int a = 0; a < 2; a++)
#pragma unroll
        for (int bb = 0; bb < 2; bb++) {
            int i = rb + ty + 16 * a;
            int j = cb + tx + 16 * bb;
            float w = __expf(-acc[a][bb] * 0.25f);
            float pair = g_lmask[b * 128 + i] * g_lmask[b * 128 + j];
            float diag = (i == j) ? 1.f : 0.f;
            w = w * pair + diag * (1.f - pair) + diag * 1e-4f;
            g_Weps[batch * 16384 + i * 128 + j] = w;
            fro += w * w;
        }
#pragma unroll
    for (int o = 16; o > 0; o >>= 1)
        fro += __shfl_xor_sync(0xffffffffu, fro, o);
    if ((tid & 31) == 0) atomicAdd(&g_fro[batch], fro);
}

// X0 = (2/(||Weps||_F + 1e-8)) * Weps^T
__global__ void buildW_B()
{
    int batch = blockIdx.x;
    int tid = threadIdx.x;
    float s = 2.f / (sqrtf(g_fro[batch]) + 1e-8f);
    for (int e = tid; e < 16384; e += 256) {
        int i = e >> 7, j = e & 127;
        g_Xa[batch * 16384 + j * 128 + i] = s * g_Weps[batch * 16384 + e];
    }
}

// ---------------- C_q / C_k laplacian kernels --------------------------------
__global__ void lap_kernel(const float* __restrict__ tm)
{
    extern __shared__ float sh[];
    float* sql = sh;
    float* skl = sql + 128 * 65;
    float* sq  = skl + 128 * 65;
    float* sk  = sq + 64 * 65;
    int tx = threadIdx.x, ty = threadIdx.y;
    int tid = ty * 16 + tx;
    int batch = blockIdx.y;
    int b = batch >> 3, h = batch & 7;
    int n0 = blockIdx.x * 64;
    for (int e = tid; e < 8192; e += 256) {
        int r = e >> 6, d = e & 63;
        sql[r * 65 + d] = g_ql[batch * 8192 + e];
        skl[r * 65 + d] = g_kl[batch * 8192 + e];
    }
    for (int e = tid; e < 4096; e += 256) {
        int r = e >> 6, d = e & 63;
        const float* row = &g_qkv[(b * Nn + n0 + r) * 1536 + h * 64];
        sq[r * 65 + d] = row[d];
        sk[r * 65 + d] = row[512 + d];
    }
    __syncthreads();
    float accq[4][8] = {}, acck[4][8] = {};
    for (int d = 0; d < 64; d++) {
        float qf[4], kf[4], qlf[8], klf[8];
#pragma unroll
        for (int a = 0; a < 4; a++) {
            qf[a] = sq[(ty + 16 * a) * 65 + d];
            kf[a] = sk[(ty + 16 * a) * 65 + d];
        }
#pragma unroll
        for (int bb = 0; bb < 8; bb++) {
            qlf[bb] = sql[(tx + 16 * bb) * 65 + d];
            klf[bb] = skl[(tx + 16 * bb) * 65 + d];
        }
#pragma unroll
        for (int a = 0; a < 4; a++)
#pragma unroll
            for (int bb = 0; bb < 8; bb++) {
                accq[a][bb] += fabsf(qf[a] - klf[bb]);
                acck[a][bb] += fabsf(kf[a] - qlf[bb]);
            }
    }
#pragma unroll
    for (int a = 0; a < 4; a++)
#pragma unroll
        for (int bb = 0; bb < 8; bb++) {
            int n = n0 + ty + 16 * a;
            int j = tx + 16 * bb;
            float lm = g_lmask[b * 128 + j];
            g_Cq[(batch * Nn + n) * 128 + j] = __expf(-accq[a][bb] * 0.25f) * lm;
            g_Ck[(batch * Nn + n) * 128 + j] = __expf(-acck[a][bb] * 0.25f) * lm;
        }
}

// ---------------- whitening stats --------------------------------------------
__global__ void stats_part(const float* __restrict__ tm)
{
    int h = blockIdx.y;
    int s = blockIdx.x;
    int j = threadIdx.x;
    float a1 = 0.f, b0 = 0.f, b1 = 0.f, b2 = 0.f;
    for (int r = 0; r < 128; r++) {
        int row = s * 128 + r;
        int b = row >> 10, n = row & 1023;
        float t = tm[row];
        float c = g_Cq[((b * 8 + h) * Nn + n) * 128 + j];
        float tc = t * c;
        a1 += tc;
        b0 += t * t;
        b1 += t * tc;
        b2 += tc * tc;
    }
    atomicAdd(&g_stats[0 * 1024 + h * 128 + j], a1);
    atomicAdd(&g_stats[1 * 1024 + h * 128 + j], b0);
    atomicAdd(&g_stats[2 * 1024 + h * 128 + j], b1);
    atomicAdd(&g_stats[3 * 1024 + h * 128 + j], b2);
}

__global__ void stats_fin()
{
    int i = blockIdx.x * 256 + threadIdx.x;
    if (i >= Hc * Mc) return;
    float valid = g_valid[0];
    float a1 = g_stats[i], b0 = g_stats[1024 + i], b1 = g_stats[2048 + i], b2 = g_stats[3072 + i];
    float mu = a1 / valid;
    float var = (b2 - 2.f * mu * b1 + mu * mu * b0) / valid;
    g_mu[i] = mu;
    g_rstd[i] = 1.f / sqrtf(var + 1e-5f);
}

// ---------------- ckv partials (f32x2 along d) -------------------------------
__global__ void ckv_part_kernel()
{
    extern __shared__ float sh[];
    float* sCk = sh;
    float* sV  = sh + 16384;
    int tx = threadIdx.x, ty = threadIdx.y;
    int tid = ty * 16 + tx;
    int batch = blockIdx.y, split = blockIdx.x;
    int b = batch >> 3, h = batch & 7;
    int n0 = split * 128;
    for (int e = tid; e < 16384; e += 256)
        sCk[e] = g_Ck[(batch * Nn + n0 + (e >> 7)) * 128 + (e & 127)];
    for (int e = tid; e < 8192; e += 256)
        sV[e] = g_qkv[(b * Nn + n0 + (e >> 6)) * 1536 + 1024 + h * 64 + (e & 63)];
    __syncthreads();
    ull acc[8][2] = {};
    for (int n = 0; n < 128; n++) {
        ull cd[8];
#pragma unroll
        for (int a = 0; a < 8; a++) cd[a] = dup2(sCk[n * 128 + ty + 16 * a]);
        ull v0 = *(const ull*)&sV[n * 64 + 2 * tx];
        ull v1 = *(const ull*)&sV[n * 64 + 2 * tx + 32];
#pragma unroll
        for (int a = 0; a < 8; a++) {
            ffma2(acc[a][0], cd[a], v0);
            ffma2(acc[a][1], cd[a], v1);
        }
    }
#pragma unroll
    for (int a = 0; a < 8; a++) {
        int j = ty + 16 * a;
        float* dst = &g_ckvp[((batch * 8 + split) * 128 + j) * 64];
        *(float2*)&dst[2 * tx]      = unpack2(acc[a][0]);
        *(float2*)&dst[2 * tx + 32] = unpack2(acc[a][1]);
    }
}

// ---------------- context = W_inv @ ckv --------------------------------------
__global__ void ctx_kernel()
{
    extern __shared__ float sh[];
    float* sW = sh;
    float* sC = sh + 16384;
    int tx = threadIdx.x, ty = threadIdx.y;
    int tid = ty * 16 + tx;
    int batch = blockIdx.x;
    for (int e = tid; e < 16384; e += 256)
        sW[e] = g_Xb[batch * 16384 + e];
    for (int e = tid; e < 8192; e += 256) {
        float s = 0.f;
#pragma unroll
        for (int p = 0; p < 8; p++) s += g_ckvp[(batch * 8 + p) * 8192 + e];
        sC[e] = s;
    }
    __syncthreads();
    ull acc[8][2] = {};
    for (int j = 0; j < 128; j++) {
        ull wd[8];
#pragma unroll
        for (int a = 0; a < 8; a++) wd[a] = dup2(sW[(ty + 16 * a) * 128 + j]);
        ull c0 = *(const ull*)&sC[j * 64 + 2 * tx];
        ull c1 = *(const ull*)&sC[j * 64 + 2 * tx + 32];
#pragma unroll
        for (int a = 0; a < 8; a++) {
            ffma2(acc[a][0], wd[a], c0);
            ffma2(acc[a][1], wd[a], c1);
        }
    }
#pragma unroll
    for (int a = 0; a < 8; a++) {
        float* dst = &g_ctx[batch * 8192 + (ty + 16 * a) * 64];
        *(float2*)&dst[2 * tx]      = unpack2(acc[a][0]);
        *(float2*)&dst[2 * tx + 32] = unpack2(acc[a][1]);
    }
}

// ---------------- ga = (C_q_norm @ context) * mh -----------------------------
__global__ void ga_kernel(const float* __restrict__ tm)
{
    extern __shared__ float sh[];
    float* sCq = sh;
    float* sC  = sh + 16384;
    int tx = threadIdx.x, ty = threadIdx.y;
    int tid = ty * 16 + tx;
    int batch = blockIdx.y, nt = blockIdx.x;
    int b = batch >> 3, h = batch & 7;
    int n0 = nt * 128;
    for (int e = tid; e < 16384; e += 256) {
        int nl = e >> 7, j = e & 127;
        float t = tm[b * Nn + n0 + nl];
        sCq[e] = (g_Cq[(batch * Nn + n0 + nl) * 128 + j] - g_mu[h * 128 + j]) * g_rstd[h * 128 + j] * t;
    }
    for (int e = tid; e < 8192; e += 256)
        sC[e] = g_ctx[batch * 8192 + e];
    __syncthreads();
    ull acc[8][2] = {};
    for (int j = 0; j < 128; j++) {
        ull qd[8];
#pragma unroll
        for (int a = 0; a < 8; a++) qd[a] = dup2(sCq[(ty + 16 * a) * 128 + j]);
        ull c0 = *(const ull*)&sC[j * 64 + 2 * tx];
        ull c1 = *(const ull*)&sC[j * 64 + 2 * tx + 32];
#pragma unroll
        for (int a = 0; a < 8; a++) {
            ffma2(acc[a][0], qd[a], c0);
            ffma2(acc[a][1], qd[a], c1);
        }
    }
#pragma unroll
    for (int a = 0; a < 8; a++) {
        int n = n0 + ty + 16 * a;
        float t = tm[b * Nn + n];
        float2 v0 = unpack2(acc[a][0]);
        float2 v1 = unpack2(acc[a][1]);
        v0.x *= t; v0.y *= t; v1.x *= t; v1.y *= t;
        float* dst = &g_gab[(b * Nn + n) * 512 + h * 64];
        *(float2*)&dst[2 * tx]      = v0;
        *(float2*)&dst[2 * tx + 32] = v1;
    }
}

// ---------------- depthwise "conv" on the scrambled flat view ----------------
__global__ void vlocal_kernel(const float* __restrict__ tm, const float* __restrict__ dw,
                              const float* __restrict__ db)
{
    int i = blockIdx.x * 256 + threadIdx.x;
    int n2 = i & 1023;
    int ch = (i >> 10) & 511;
    int b  = i >> 19;
    float w0 = dw[ch * 3 + 0], w1 = dw[ch * 3 + 1], w2 = dw[ch * 3 + 2];
    int f = ch * 1024 + n2;
    float acc = db[ch];
    if (n2 > 0) {
        int ff = f - 1;
        acc += w0 * g_qkv[(b * Nn + (ff >> 9)) * 1536 + 1024 + (ff & 511)];
    }
    acc += w1 * g_qkv[(b * Nn + (f >> 9)) * 1536 + 1024 + (f & 511)];
    if (n2 < 1023) {
        int ff = f + 1;
        acc += w2 * g_qkv[(b * Nn + (ff >> 9)) * 1536 + 1024 + (ff & 511)];
    }
    g_gab[(b * Nn + n2) * 512 + ch] += acc * tm[b * Nn + n2];
}

// ---------------- launch -----------------------------------------------------
extern "C" void kernel_launch(void* const* d_in, const int* in_sizes, int n_in,
                              void* d_out, int out_size)
{
    const float* x      = (const float*)d_in[0];
    const float* tm     = (const float*)d_in[1];
    const float* qkv_w  = (const float*)d_in[2];
    const float* qkv_b  = (const float*)d_in[3];
    const float* proj_w = (const float*)d_in[4];
    const float* proj_b = (const float*)d_in[5];
    const float* dwc_w  = (const float*)d_in[6];
    const float* dwc_b  = (const float*)d_in[7];
    float* out = (float*)d_out;

    float *p_qkv, *p_gab, *p_Weps, *p_Xa, *p_Xb, *p_T;
    cudaGetSymbolAddress((void**)&p_qkv,  g_qkv);
    cudaGetSymbolAddress((void**)&p_gab,  g_gab);
    cudaGetSymbolAddress((void**)&p_Weps, g_Weps);
    cudaGetSymbolAddress((void**)&p_Xa,   g_Xa);
    cudaGetSymbolAddress((void**)&p_Xb,   g_Xb);
    cudaGetSymbolAddress((void**)&p_T,    g_T);

    cudaFuncSetAttribute(lap_kernel,      cudaFuncAttributeMaxDynamicSharedMemorySize, 99840);
    cudaFuncSetAttribute(ckv_part_kernel, cudaFuncAttributeMaxDynamicSharedMemorySize, 98304);
    cudaFuncSetAttribute(ctx_kernel,      cudaFuncAttributeMaxDynamicSharedMemorySize, 98304);
    cudaFuncSetAttribute(ga_kernel,       cudaFuncAttributeMaxDynamicSharedMemorySize, 98304);

    dim3 blk(16, 16);

    // 1. masked QKV projection (128x64 tiles, pipelined)
    gemm_bias_mask<<<dim3(1536 / 64, 2048 / 128), blk>>>(x, qkv_w, qkv_b, tm, p_qkv,
                                                         Bn * Nn, 3 * Cc, Cc);
    // 2. pooled-mask stats + pooled q_l/k_l
    pm_kernel<<<1, 256>>>(tm);
    pool_kernel<<<1024, 256>>>(tm);

    // 3. W_eps + X0, Newton-Schulz (5 iters)
    buildW_A<<<dim3(4, 4, 16), blk>>>();
    buildW_B<<<16, 256>>>();
    float* Xc = p_Xa;
    float* Xn = p_Xb;
    for (int it = 0; it < 5; it++) {
        ns_mm<<<dim3(2, 4, 16), blk>>>(p_Weps, Xc, p_T, 1);   // T = 2I - Weps@X
        ns_mm<<<dim3(2, 4, 16), blk>>>(Xc, p_T, Xn, 0);       // X = X@T
        float* t = Xc; Xc = Xn; Xn = t;
    }
    // result in g_Xb

    // 4. C_q / C_k
    lap_kernel<<<dim3(16, 16), blk, 99840>>>(tm);

    // 5. whitening stats
    stats_part<<<dim3(16, 8), 128>>>(tm);
    stats_fin<<<4, 256>>>();

    // 6. context = W_inv @ (Ck^T @ v)
    ckv_part_kernel<<<dim3(8, 16), blk, 98304>>>();
    ctx_kernel<<<16, blk, 98304>>>();

    // 7. ga + depthwise local term
    ga_kernel<<<dim3(8, 16), blk, 98304>>>(tm);
    vlocal_kernel<<<4096, 256>>>(tm, dwc_w, dwc_b);

    // 8. output projection
    gemm_bias_mask<<<dim3(512 / 64, 2048 / 128), blk>>>(p_gab, proj_w, proj_b, tm, out,
                                                        Bn * Nn, Cc, Cc);
}